// round 11
// baseline (speedup 1.0000x reference)
#include <cuda_runtime.h>
#include <cstdint>

// Depthwise 3D conv 3x3x3, SAME, stride 1.
// x: (N=4, D=16, H=112, W=112, C=64) f32, NDHWC
// w: (3,3,3,1,64) f32 -> idx ((kd*3+kh)*3+kw)*64 + c
//
// R11 vs R10: re-tile to HPT=4, WPT=4 (thread = 4 h-rows x 4 w x 2 channels).
// Input loads drop 120->108 per thread (135 vs 147 total LDG, -8% l1tex
// wavefronts) at identical FMA count and ~equal regs: all 9 taps of one kd
// plane stay live (18 regs) instead of a 2-deep rotation, acc 16 ull, rv[6].
// 18 small 6-LDG bursts interleave with FMAs more smoothly than 12x10.
// Interior/edge block split retained; __launch_bounds__(64,14).

#define N_  4
#define D_  16
#define H_  112
#define W_  112
#define C_  64
#define WPT 4          // outputs per thread along W
#define HPT 4          // outputs per thread along H
#define CS  (C_ / 2)   // 32 ull per spatial position

typedef unsigned long long ull;

__device__ __forceinline__ ull ffma2(ull a, ull b, ull c) {
    ull d;
    asm("fma.rn.f32x2 %0, %1, %2, %3;" : "=l"(d) : "l"(a), "l"(b), "l"(c));
    return d;
}

template <bool INT>
__device__ __forceinline__ void conv_body(
    const ull* __restrict__ xp, const ull* __restrict__ swp,
    ull* __restrict__ out, int n, int d, int h0, int w0, int tx) {

    const bool wlo = INT || (w0 > 0);
    const bool whi = INT || (w0 + WPT < W_);

    ull acc[HPT][WPT];
#pragma unroll
    for (int j = 0; j < HPT; j++)
#pragma unroll
        for (int i = 0; i < WPT; i++) acc[j][i] = 0ull;

#pragma unroll
    for (int kd = 0; kd < 3; kd++) {
        const int zd = d + kd - 1;
        if (!INT && (unsigned)zd >= D_) continue;

        // all 9 taps of this kd plane (channel pair tx)
        ull wt[3][3];
#pragma unroll
        for (int kh = 0; kh < 3; kh++)
#pragma unroll
            for (int kw = 0; kw < 3; kw++)
                wt[kh][kw] = swp[((kd * 3 + kh) * 3 + kw) * CS + tx];

        // pointer to (n, zd, h0-1, w0, tx); advances one h-row per r
        const ull* rowp =
            xp + ((((n * D_ + zd) * H_ + (h0 - 1)) * W_ + w0) * CS + tx);

#pragma unroll
        for (int r = 0; r < HPT + 2; r++) {    // zh = h0-1 .. h0+4
            const int zh = h0 - 1 + r;
            const bool rowOk = INT || ((unsigned)zh < H_);

            if (rowOk) {
                // batched row preload: 6 LDGs, immediate offsets
                ull rv[WPT + 2];
                rv[0] = wlo ? rowp[-CS] : 0ull;
#pragma unroll
                for (int q = 0; q < WPT; q++)
                    rv[q + 1] = rowp[q * CS];
                rv[WPT + 1] = whi ? rowp[WPT * CS] : 0ull;

                // row r feeds outputs j = r-2..r (kh = r-j), clamped to 0..3
#pragma unroll
                for (int j = 0; j < HPT; j++) {
                    if (j <= r && r <= j + 2) {
                        const int kh = r - j;
#pragma unroll
                        for (int i = 0; i < WPT; i++) {
                            acc[j][i] = ffma2(rv[i],     wt[kh][0], acc[j][i]);
                            acc[j][i] = ffma2(rv[i + 1], wt[kh][1], acc[j][i]);
                            acc[j][i] = ffma2(rv[i + 2], wt[kh][2], acc[j][i]);
                        }
                    }
                }
            }
            rowp += W_ * CS;
        }
    }

    ull* __restrict__ op =
        out + ((((n * D_ + d) * H_ + h0) * W_ + w0) * CS + tx);
#pragma unroll
    for (int j = 0; j < HPT; j++)
#pragma unroll
        for (int i = 0; i < WPT; i++)
            op[(j * W_ + i) * CS] = acc[j][i];
}

__global__ void __launch_bounds__(64, 14)
dwconv3d_kernel(const float* __restrict__ x,
                const float* __restrict__ wgt,
                float* __restrict__ out) {
    const ull* __restrict__ swp = reinterpret_cast<const ull*>(wgt);
    const ull* __restrict__ xp  = reinterpret_cast<const ull*>(x);
    ull* __restrict__ op        = reinterpret_cast<ull*>(out);

    const int tx = threadIdx.x;                        // channel pair 0..31
    const int h0 = blockIdx.y * 8 + threadIdx.y * 4;   // 0,4,...,108
    const int w0 = blockIdx.x * WPT;                   // 0,4,...,108
    const int nd = blockIdx.z;
    const int n  = nd >> 4;
    const int d  = nd & 15;

    // Block-uniform interior test: no d/h/w halo clamping anywhere in block.
    const bool interior =
        (d >= 1) && (d <= 14) &&
        (blockIdx.y >= 1) && (blockIdx.y <= (H_ / 8) - 2) &&
        (blockIdx.x >= 1) && (blockIdx.x <= (W_ / WPT) - 2);

    if (interior)
        conv_body<true>(xp, swp, op, n, d, h0, w0, tx);
    else
        conv_body<false>(xp, swp, op, n, d, h0, w0, tx);
}

extern "C" void kernel_launch(void* const* d_in, const int* in_sizes, int n_in,
                              void* d_out, int out_size) {
    const float* x = (const float*)d_in[0];
    const float* w = (const float*)d_in[1];
    float* o = (float*)d_out;

    dim3 block(32, 2, 1);                        // 64 threads
    dim3 grid(W_ / WPT, H_ / 8, N_ * D_);        // 28 x 14 x 64
    dwconv3d_kernel<<<grid, block>>>(x, w, o);
}

// round 12
// speedup vs baseline: 1.0863x; 1.0863x over previous
#include <cuda_runtime.h>
#include <cstdint>

// Depthwise 3D conv 3x3x3, SAME, stride 1.
// x: (4,16,112,112,64) f32 NDHWC; w: (3,3,3,1,64) f32.
//
// Thread: 2 channels (f32x2), 8 w-outputs, 2 h-rows (R9 tile — proven optimum).
// R12 vs R9: interior blocks run a DOUBLE-BUFFERED row pipeline (row r+1's
// 10-LDG burst issues before row r's 48 packed FMAs) under a (64,11) register
// cap, so ptxas builds a bounded partial overlap instead of R5's unbounded
// 138-reg pipeline. Edge blocks keep the single-buffer guarded body.

#define N_  4
#define D_  16
#define H_  112
#define W_  112
#define C_  64
#define WPT 8
#define CS  (C_ / 2)   // 32 ull per spatial position
#define ROWSTEP (W_ * CS)

typedef unsigned long long ull;

__device__ __forceinline__ ull ffma2(ull a, ull b, ull c) {
    ull d;
    asm("fma.rn.f32x2 %0, %1, %2, %3;" : "=l"(d) : "l"(a), "l"(b), "l"(c));
    return d;
}

// ---------------- interior: guard-free, double-buffered row pipeline --------
__device__ __forceinline__ void conv_interior(
    const ull* __restrict__ xp, const ull* __restrict__ swp,
    ull* __restrict__ out, int n, int d, int h0, int w0, int tx) {

    ull acc0[WPT], acc1[WPT];
#pragma unroll
    for (int i = 0; i < WPT; i++) { acc0[i] = 0ull; acc1[i] = 0ull; }

#pragma unroll
    for (int kd = 0; kd < 3; kd++) {
        const int zd = d + kd - 1;                    // always in [0,15]
        const ull* rowp =
            xp + ((((n * D_ + zd) * H_ + (h0 - 1)) * W_ + w0) * CS + tx);

        ull wa0 = 0, wa1 = 0, wa2 = 0;
        ull wb0, wb1, wb2;

        ull buf[2][WPT + 2];

        // prime: row r=0 (zh = h0-1), 10 unconditional LDGs
#pragma unroll
        for (int j = 0; j < WPT + 2; j++)
            buf[0][j] = rowp[(j - 1) * CS];

#pragma unroll
        for (int r = 0; r < 4; r++) {                 // zh = h0-1+r
            // prefetch next row into the other buffer BEFORE this row's FMAs
            if (r < 3) {
                const ull* np = rowp + ROWSTEP;
#pragma unroll
                for (int j = 0; j < WPT + 2; j++)
                    buf[(r + 1) & 1][j] = np[(j - 1) * CS];
            }

            // weight rotate + fetch (drains under prefetch latency)
            wb0 = wa0; wb1 = wa1; wb2 = wa2;
            if (r < 3) {
                const int base = (kd * 9 + r * 3) * CS + tx;
                wa0 = swp[base];
                wa1 = swp[base + CS];
                wa2 = swp[base + 2 * CS];
            }

            const ull* rv = buf[r & 1];
#pragma unroll
            for (int i = 0; i < WPT; i++) {
                if (r <= 2) {                          // output h0, kh=r
                    acc0[i] = ffma2(rv[i],     wa0, acc0[i]);
                    acc0[i] = ffma2(rv[i + 1], wa1, acc0[i]);
                    acc0[i] = ffma2(rv[i + 2], wa2, acc0[i]);
                }
                if (r >= 1) {                          // output h0+1, kh=r-1
                    acc1[i] = ffma2(rv[i],     wb0, acc1[i]);
                    acc1[i] = ffma2(rv[i + 1], wb1, acc1[i]);
                    acc1[i] = ffma2(rv[i + 2], wb2, acc1[i]);
                }
            }
            rowp += ROWSTEP;
        }
    }

    ull* __restrict__ op =
        out + ((((n * D_ + d) * H_ + h0) * W_ + w0) * CS + tx);
#pragma unroll
    for (int i = 0; i < WPT; i++) {
        op[i * CS] = acc0[i];
        op[ROWSTEP + i * CS] = acc1[i];
    }
}

// ---------------- edge: guarded single-buffer (R9 body) ---------------------
__device__ __forceinline__ void conv_edge(
    const ull* __restrict__ xp, const ull* __restrict__ swp,
    ull* __restrict__ out, int n, int d, int h0, int w0, int tx) {

    const bool wlo = (w0 > 0);
    const bool whi = (w0 + WPT < W_);

    ull acc0[WPT], acc1[WPT];
#pragma unroll
    for (int i = 0; i < WPT; i++) { acc0[i] = 0ull; acc1[i] = 0ull; }

#pragma unroll
    for (int kd = 0; kd < 3; kd++) {
        const int zd = d + kd - 1;
        if ((unsigned)zd >= D_) continue;

        const ull* rowp =
            xp + ((((n * D_ + zd) * H_ + (h0 - 1)) * W_ + w0) * CS + tx);

        ull wa0 = 0, wa1 = 0, wa2 = 0;
        ull wb0, wb1, wb2;

#pragma unroll
        for (int r = 0; r < 4; r++) {
            const int zh = h0 - 1 + r;
            const bool rowOk = ((unsigned)zh < H_);

            ull rv[WPT + 2];
            if (rowOk) {
                rv[0] = wlo ? rowp[-CS] : 0ull;
#pragma unroll
                for (int j = 0; j < WPT; j++)
                    rv[j + 1] = rowp[j * CS];
                rv[WPT + 1] = whi ? rowp[WPT * CS] : 0ull;
            }

            wb0 = wa0; wb1 = wa1; wb2 = wa2;
            if (r < 3) {
                const int base = (kd * 9 + r * 3) * CS + tx;
                wa0 = swp[base];
                wa1 = swp[base + CS];
                wa2 = swp[base + 2 * CS];
            }

            if (rowOk) {
#pragma unroll
                for (int i = 0; i < WPT; i++) {
                    if (r <= 2) {
                        acc0[i] = ffma2(rv[i],     wa0, acc0[i]);
                        acc0[i] = ffma2(rv[i + 1], wa1, acc0[i]);
                        acc0[i] = ffma2(rv[i + 2], wa2, acc0[i]);
                    }
                    if (r >= 1) {
                        acc1[i] = ffma2(rv[i],     wb0, acc1[i]);
                        acc1[i] = ffma2(rv[i + 1], wb1, acc1[i]);
                        acc1[i] = ffma2(rv[i + 2], wb2, acc1[i]);
                    }
                }
            }
            rowp += ROWSTEP;
        }
    }

    ull* __restrict__ op =
        out + ((((n * D_ + d) * H_ + h0) * W_ + w0) * CS + tx);
#pragma unroll
    for (int i = 0; i < WPT; i++) {
        op[i * CS] = acc0[i];
        op[ROWSTEP + i * CS] = acc1[i];
    }
}

__global__ void __launch_bounds__(64, 11)
dwconv3d_kernel(const float* __restrict__ x,
                const float* __restrict__ wgt,
                float* __restrict__ out) {
    const ull* __restrict__ swp = reinterpret_cast<const ull*>(wgt);
    const ull* __restrict__ xp  = reinterpret_cast<const ull*>(x);
    ull* __restrict__ op        = reinterpret_cast<ull*>(out);

    const int tx = threadIdx.x;                       // channel pair 0..31
    const int h0 = blockIdx.y * 4 + threadIdx.y * 2;  // even rows 0..110
    const int w0 = blockIdx.x * WPT;                  // 0..104
    const int nd = blockIdx.z;
    const int n  = nd >> 4;
    const int d  = nd & 15;

    const bool interior =
        (d >= 1) && (d <= 14) &&
        (blockIdx.y >= 1) && (blockIdx.y <= (H_ / 4) - 2) &&
        (blockIdx.x >= 1) && (blockIdx.x <= (W_ / WPT) - 2);

    if (interior)
        conv_interior(xp, swp, op, n, d, h0, w0, tx);
    else
        conv_edge(xp, swp, op, n, d, h0, w0, tx);
}

extern "C" void kernel_launch(void* const* d_in, const int* in_sizes, int n_in,
                              void* d_out, int out_size) {
    const float* x = (const float*)d_in[0];
    const float* w = (const float*)d_in[1];
    float* o = (float*)d_out;

    dim3 block(32, 2, 1);                        // 64 threads
    dim3 grid(W_ / WPT, H_ / 4, N_ * D_);        // 14 x 28 x 64
    dwconv3d_kernel<<<grid, block>>>(x, w, o);
}